// round 14
// baseline (speedup 1.0000x reference)
#include <cuda_runtime.h>
#include <math.h>

#define EMB 128
#define BATCH 8192
#define NTHREADS 128
#define NWARPS 4
#define FULLMASK 0xffffffffu

__device__ int g_seg_start[BATCH + 1];

// Vectorized boundary scan: thread i covers tokens 4i..4i+3 via one int4 load.
__global__ void bounds_scan_kernel(const int* __restrict__ seg, int T) {
    const int i = blockIdx.x * blockDim.x + threadIdx.x;
    const int base = i * 4;
    if (base >= T) return;

    if (base + 3 < T) {
        const int4 s4 = *reinterpret_cast<const int4*>(seg + base);
        int prev;
        if (base == 0) {
            for (int b = 0; b <= s4.x; b++) g_seg_start[b] = 0;
            prev = s4.x;
        } else {
            prev = seg[base - 1];
            for (int b = prev + 1; b <= s4.x; b++) g_seg_start[b] = base;
            prev = s4.x;
        }
        for (int b = prev + 1; b <= s4.y; b++) g_seg_start[b] = base + 1;
        for (int b = s4.y + 1; b <= s4.z; b++) g_seg_start[b] = base + 2;
        for (int b = s4.z + 1; b <= s4.w; b++) g_seg_start[b] = base + 3;
        if (base + 4 == T) {
            for (int b = s4.w + 1; b <= BATCH; b++) g_seg_start[b] = T;
        }
    } else {
        for (int j = base; j < T; j++) {
            const int s = seg[j];
            if (j == 0) {
                for (int b = 0; b <= s; b++) g_seg_start[b] = 0;
            } else {
                const int prev = seg[j - 1];
                for (int b = prev + 1; b <= s; b++) g_seg_start[b] = j;
            }
            if (j == T - 1) {
                for (int b = s + 1; b <= BATCH; b++) g_seg_start[b] = T;
            }
        }
    }
}

__global__ __launch_bounds__(NTHREADS, 12)
void fattn_kernel(const float* __restrict__ value,
                  const float* __restrict__ key,
                  const float* __restrict__ fingerprint,
                  const float* __restrict__ w,
                  float* __restrict__ out) {
    __shared__ float4 wsum[NWARPS][64];   // value cols idx 0..31, key cols 32..63
    __shared__ float zred[NWARPS];
    __shared__ float dwf[EMB];

    const int b    = blockIdx.x;
    const int tid  = threadIdx.x;
    const int wid  = tid >> 5;
    const int lane = tid & 31;

    const int start = g_seg_start[b];
    const int end   = g_seg_start[b + 1];
    const int n     = end - start;

    dwf[tid] = w[tid * EMB + tid] * fingerprint[tid];   // one thread per column
    __syncthreads();

    const float d0 = dwf[lane * 4 + 0];
    const float d1 = dwf[lane * 4 + 1];
    const float d2 = dwf[lane * 4 + 2];
    const float d3 = dwf[lane * 4 + 3];
    const float inv_scale = 0.08838834764831845f; // 1/sqrt(128)
    const bool lo_half = (lane < 16);

    float4 accV = make_float4(0.f, 0.f, 0.f, 0.f);
    float4 accK = make_float4(0.f, 0.f, 0.f, 0.f);
    float z = 0.f;

    const float* kbase = key   + (long long)start * EMB + lane * 4;
    const float* vbase = value + (long long)start * EMB + lane * 4;

    int t = wid * 2;
    for (; t + 1 < n; t += 2 * NWARPS) {
        const float4 k0 = *reinterpret_cast<const float4*>(kbase + (long long)t * EMB);
        const float4 k1 = *reinterpret_cast<const float4*>(kbase + (long long)(t + 1) * EMB);
        const float4 v0 = *reinterpret_cast<const float4*>(vbase + (long long)t * EMB);
        const float4 v1 = *reinterpret_cast<const float4*>(vbase + (long long)(t + 1) * EMB);

        float p0 = (k0.x * d0 + k0.y * d1) + (k0.z * d2 + k0.w * d3);
        float p1 = (k1.x * d0 + k1.y * d1) + (k1.z * d2 + k1.w * d3);
        // Split butterfly: 7 SHFL + 1 MUFU for two tokens.
        p0 += __shfl_xor_sync(FULLMASK, p0, 16);
        p1 += __shfl_xor_sync(FULLMASK, p1, 16);
        float q = lo_half ? p0 : p1;
        #pragma unroll
        for (int o = 8; o > 0; o >>= 1) q += __shfl_xor_sync(FULLMASK, q, o);
        const float e  = __expf(q * inv_scale);
        const float eo = __shfl_xor_sync(FULLMASK, e, 16);
        const float e0 = lo_half ? e : eo;
        const float e1 = lo_half ? eo : e;

        z += e0 + e1;
        accK.x += e0 * k0.x + e1 * k1.x;
        accK.y += e0 * k0.y + e1 * k1.y;
        accK.z += e0 * k0.z + e1 * k1.z;
        accK.w += e0 * k0.w + e1 * k1.w;
        accV.x += e0 * v0.x + e1 * v1.x;
        accV.y += e0 * v0.y + e1 * v1.y;
        accV.z += e0 * v0.z + e1 * v1.z;
        accV.w += e0 * v0.w + e1 * v1.w;
    }
    if (t < n) {  // tail token
        const float4 k0 = *reinterpret_cast<const float4*>(kbase + (long long)t * EMB);
        const float4 v0 = *reinterpret_cast<const float4*>(vbase + (long long)t * EMB);
        float p0 = (k0.x * d0 + k0.y * d1) + (k0.z * d2 + k0.w * d3);
        #pragma unroll
        for (int o = 16; o > 0; o >>= 1) p0 += __shfl_xor_sync(FULLMASK, p0, o);
        const float e0 = __expf(p0 * inv_scale);
        z += e0;
        accK.x += e0 * k0.x; accK.y += e0 * k0.y;
        accK.z += e0 * k0.z; accK.w += e0 * k0.w;
        accV.x += e0 * v0.x; accV.y += e0 * v0.y;
        accV.z += e0 * v0.z; accV.w += e0 * v0.w;
    }

    wsum[wid][lane]      = accV;
    wsum[wid][32 + lane] = accK;
    if (lane == 0) zred[wid] = z;
    __syncthreads();

    const float zz = (zred[0] + zred[1]) + (zred[2] + zred[3]);
    const float invZ = (zz > 0.f) ? (1.f / zz) : 0.f;

    // Each thread produces 2 output columns: tid and tid+128.
    const float* ws = reinterpret_cast<const float*>(wsum);  // [4][256]
    const float a0 = ws[0 * 256 + tid],       a1 = ws[1 * 256 + tid];
    const float a2 = ws[2 * 256 + tid],       a3 = ws[3 * 256 + tid];
    const float b0 = ws[0 * 256 + 128 + tid], b1 = ws[1 * 256 + 128 + tid];
    const float b2 = ws[2 * 256 + 128 + tid], b3 = ws[3 * 256 + 128 + tid];
    float* orow = out + (long long)b * (2 * EMB);
    orow[tid]       = ((a0 + a1) + (a2 + a3)) * invZ;
    orow[tid + 128] = ((b0 + b1) + (b2 + b3)) * invZ;
}

extern "C" void kernel_launch(void* const* d_in, const int* in_sizes, int n_in,
                              void* d_out, int out_size) {
    const float* value = (const float*)d_in[0];
    const float* key   = (const float*)d_in[1];
    const int*   seg   = (const int*)d_in[2];
    const float* fp    = (const float*)d_in[3];
    const float* w     = (const float*)d_in[4];
    float* out = (float*)d_out;
    const int T = in_sizes[2];

    const int nthreads_bounds = 256;
    const int nblocks_bounds = ((T + 3) / 4 + nthreads_bounds - 1) / nthreads_bounds;
    bounds_scan_kernel<<<nblocks_bounds, nthreads_bounds>>>(seg, T);
    fattn_kernel<<<BATCH, NTHREADS>>>(value, key, fp, w, out);
}

// round 15
// speedup vs baseline: 1.0142x; 1.0142x over previous
#include <cuda_runtime.h>
#include <math.h>

#define EMB 128
#define BATCH 8192
#define NTHREADS 256
#define FULLMASK 0xffffffffu

__device__ int g_seg_start[BATCH + 1];

// Vectorized boundary scan: thread i covers tokens 4i..4i+3 via one int4 load.
__global__ void bounds_scan_kernel(const int* __restrict__ seg, int T) {
    const int i = blockIdx.x * blockDim.x + threadIdx.x;
    const int base = i * 4;
    if (base >= T) return;

    if (base + 3 < T) {
        const int4 s4 = *reinterpret_cast<const int4*>(seg + base);
        int prev;
        if (base == 0) {
            for (int b = 0; b <= s4.x; b++) g_seg_start[b] = 0;
            prev = s4.x;
        } else {
            prev = seg[base - 1];
            for (int b = prev + 1; b <= s4.x; b++) g_seg_start[b] = base;
            prev = s4.x;
        }
        for (int b = prev + 1; b <= s4.y; b++) g_seg_start[b] = base + 1;
        for (int b = s4.y + 1; b <= s4.z; b++) g_seg_start[b] = base + 2;
        for (int b = s4.z + 1; b <= s4.w; b++) g_seg_start[b] = base + 3;
        if (base + 4 == T) {
            for (int b = s4.w + 1; b <= BATCH; b++) g_seg_start[b] = T;
        }
    } else {
        for (int j = base; j < T; j++) {
            const int s = seg[j];
            if (j == 0) {
                for (int b = 0; b <= s; b++) g_seg_start[b] = 0;
            } else {
                const int prev = seg[j - 1];
                for (int b = prev + 1; b <= s; b++) g_seg_start[b] = j;
            }
            if (j == T - 1) {
                for (int b = s + 1; b <= BATCH; b++) g_seg_start[b] = T;
            }
        }
    }
}

__global__ __launch_bounds__(NTHREADS, 6)
void fattn_kernel(const float* __restrict__ value,
                  const float* __restrict__ key,
                  const float* __restrict__ fingerprint,
                  const float* __restrict__ w,
                  float* __restrict__ out) {
    __shared__ float4 wsum[8][64];   // value cols idx 0..31, key cols 32..63
    __shared__ float zred[8];

    const int b    = blockIdx.x;
    const int tid  = threadIdx.x;
    const int wid  = tid >> 5;
    const int lane = tid & 31;

    const int start = g_seg_start[b];
    const int end   = g_seg_start[b + 1];
    const int n     = end - start;

    // Warp-local dwf: no smem, no prologue barrier. w diag is L2-hot (64 KB).
    const int c = lane * 4;
    const float4 f = *reinterpret_cast<const float4*>(fingerprint + c);
    const float d0 = __ldg(w + (long long)(c + 0) * EMB + (c + 0)) * f.x;
    const float d1 = __ldg(w + (long long)(c + 1) * EMB + (c + 1)) * f.y;
    const float d2 = __ldg(w + (long long)(c + 2) * EMB + (c + 2)) * f.z;
    const float d3 = __ldg(w + (long long)(c + 3) * EMB + (c + 3)) * f.w;
    const float inv_scale = 0.08838834764831845f; // 1/sqrt(128)
    const bool lo_half = (lane < 16);

    float4 accV = make_float4(0.f, 0.f, 0.f, 0.f);
    float4 accK = make_float4(0.f, 0.f, 0.f, 0.f);
    float z = 0.f;

    const float* kbase = key   + (long long)start * EMB + c;
    const float* vbase = value + (long long)start * EMB + c;

    int t = wid * 2;
    for (; t + 1 < n; t += 16) {
        const float4 k0 = *reinterpret_cast<const float4*>(kbase + (long long)t * EMB);
        const float4 k1 = *reinterpret_cast<const float4*>(kbase + (long long)(t + 1) * EMB);
        const float4 v0 = *reinterpret_cast<const float4*>(vbase + (long long)t * EMB);
        const float4 v1 = *reinterpret_cast<const float4*>(vbase + (long long)(t + 1) * EMB);

        float p0 = (k0.x * d0 + k0.y * d1) + (k0.z * d2 + k0.w * d3);
        float p1 = (k1.x * d0 + k1.y * d1) + (k1.z * d2 + k1.w * d3);
        // Split butterfly: 7 SHFL + 1 MUFU for two tokens.
        p0 += __shfl_xor_sync(FULLMASK, p0, 16);
        p1 += __shfl_xor_sync(FULLMASK, p1, 16);
        float q = lo_half ? p0 : p1;
        #pragma unroll
        for (int o = 8; o > 0; o >>= 1) q += __shfl_xor_sync(FULLMASK, q, o);
        const float e  = __expf(q * inv_scale);
        const float eo = __shfl_xor_sync(FULLMASK, e, 16);
        const float e0 = lo_half ? e : eo;
        const float e1 = lo_half ? eo : e;

        z += e0 + e1;
        accK.x += e0 * k0.x + e1 * k1.x;
        accK.y += e0 * k0.y + e1 * k1.y;
        accK.z += e0 * k0.z + e1 * k1.z;
        accK.w += e0 * k0.w + e1 * k1.w;
        accV.x += e0 * v0.x + e1 * v1.x;
        accV.y += e0 * v0.y + e1 * v1.y;
        accV.z += e0 * v0.z + e1 * v1.z;
        accV.w += e0 * v0.w + e1 * v1.w;
    }
    if (t < n) {  // tail token: plain 5-step butterfly
        const float4 k0 = *reinterpret_cast<const float4*>(kbase + (long long)t * EMB);
        const float4 v0 = *reinterpret_cast<const float4*>(vbase + (long long)t * EMB);
        float p0 = (k0.x * d0 + k0.y * d1) + (k0.z * d2 + k0.w * d3);
        #pragma unroll
        for (int o = 16; o > 0; o >>= 1) p0 += __shfl_xor_sync(FULLMASK, p0, o);
        const float e0 = __expf(p0 * inv_scale);
        z += e0;
        accK.x += e0 * k0.x; accK.y += e0 * k0.y;
        accK.z += e0 * k0.z; accK.w += e0 * k0.w;
        accV.x += e0 * v0.x; accV.y += e0 * v0.y;
        accV.z += e0 * v0.z; accV.w += e0 * v0.w;
    }

    wsum[wid][lane]      = accV;   // value cols lane*4..+3
    wsum[wid][32 + lane] = accK;   // key   cols lane*4..+3
    if (lane == 0) zred[wid] = z;  // z identical across lanes
    __syncthreads();

    const float zz = (zred[0] + zred[1]) + (zred[2] + zred[3])
                   + (zred[4] + zred[5]) + (zred[6] + zred[7]);
    const float invZ = (zz > 0.f) ? (1.f / zz) : 0.f;

    const float* ws = reinterpret_cast<const float*>(wsum);  // [8][256]
    const float a0 = ws[0 * 256 + tid], a1 = ws[1 * 256 + tid];
    const float a2 = ws[2 * 256 + tid], a3 = ws[3 * 256 + tid];
    const float a4 = ws[4 * 256 + tid], a5 = ws[5 * 256 + tid];
    const float a6 = ws[6 * 256 + tid], a7 = ws[7 * 256 + tid];
    const float acc = ((a0 + a1) + (a2 + a3)) + ((a4 + a5) + (a6 + a7));
    out[(long long)b * (2 * EMB) + tid] = acc * invZ;
}

extern "C" void kernel_launch(void* const* d_in, const int* in_sizes, int n_in,
                              void* d_out, int out_size) {
    const float* value = (const float*)d_in[0];
    const float* key   = (const float*)d_in[1];
    const int*   seg   = (const int*)d_in[2];
    const float* fp    = (const float*)d_in[3];
    const float* w     = (const float*)d_in[4];
    float* out = (float*)d_out;
    const int T = in_sizes[2];

    const int nthreads_bounds = 256;
    const int nblocks_bounds = ((T + 3) / 4 + nthreads_bounds - 1) / nthreads_bounds;
    bounds_scan_kernel<<<nblocks_bounds, nthreads_bounds>>>(seg, T);
    fattn_kernel<<<BATCH, NTHREADS>>>(value, key, fp, w, out);
}